// round 10
// baseline (speedup 1.0000x reference)
#include <cuda_runtime.h>
#include <cstdint>
#include <cstddef>

// ---------------------------------------------------------------------------
// SNN, fp32-faithful, PASSING association (round 9): per output, fp32 FMA
// chain ascending k, K split into panels [0,512),[512,1024), panel sums
// combined with one rounded add. THIS ROUND: schedule-only optimization —
// identical per-output arithmetic (f32x2 is per-lane IEEE RN), new layout:
// 512 threads/CTA (4 warps/SMSP), per-thread 4m x 8n m-packed accumulators,
// broadcast B reads, KTILE=16, single __syncthreads per k-tile.
// ---------------------------------------------------------------------------

#define NB 16384
#define NH 1024
#define NSTEPS 25
#define NO 10

// ----------------------------- device scratch ------------------------------
__device__ __align__(16) float g_spk1a[NB * NH];
__device__ __align__(16) float g_spk1b[NB * NH];
__device__ __align__(16) float g_spk2a[NB * NH];
__device__ __align__(16) float g_spk2b[NB * NH];
__device__ __align__(16) float g_mem1[NB * NH];
__device__ __align__(16) float g_mem2[NB * NH];
__device__ __align__(16) float g_cur1[NB * NH];
__device__ __align__(16) float g_cur2[NB * NH];
__device__ __align__(16) float g_ssum[NB * NH];

// --------------------------- f32x2 packed helpers ---------------------------
__device__ __forceinline__ uint64_t dup2(float x) {
    uint64_t d;
    asm("mov.b64 %0, {%1, %2};" : "=l"(d) : "f"(x), "f"(x));
    return d;
}
__device__ __forceinline__ uint64_t fma2(uint64_t a, uint64_t b, uint64_t c) {
    uint64_t d;
    asm("fma.rn.f32x2 %0, %1, %2, %3;" : "=l"(d) : "l"(a), "l"(b), "l"(c));
    return d;
}
__device__ __forceinline__ uint64_t add2(uint64_t a, uint64_t b) {
    uint64_t d;
    asm("add.rn.f32x2 %0, %1, %2;" : "=l"(d) : "l"(a), "l"(b));
    return d;
}
__device__ __forceinline__ float2 unpk2(uint64_t v) {
    float lo, hi;
    asm("mov.b64 {%0, %1}, %2;" : "=f"(lo), "=f"(hi) : "l"(v));
    return make_float2(lo, hi);
}

// ------------------------------- prep kernels ------------------------------
__global__ void init_state_kernel() {
    size_t i = (size_t)blockIdx.x * blockDim.x + threadIdx.x;
    g_mem1[i] = 0.f;
    g_mem2[i] = 0.f;
    g_ssum[i] = 0.f;
    g_spk1a[i] = 0.f;
    g_spk2a[i] = 0.f;
}

// ssum <- ssum / 25  (reference divides BEFORE the W3 matmul)
__global__ void div25_kernel(float* __restrict__ s) {
    size_t i = (size_t)blockIdx.x * blockDim.x + threadIdx.x;
    s[i] = __fdiv_rn(s[i], 25.0f);
}

// ------------------------------- GEMM kernel -------------------------------
// C[m,n] = sum_k A[m,k]*B[n,k]: panels [0,512),[512,1024), serial ascending
// k within panel, one rounded add to combine (EXACTLY as the passing R9).
// Tile 128x128, KTILE=16, 512 threads (16 warps):
//   warp w -> cols [w*8, w*8+8);  lane -> rows [lane*4, lane*4+4)
// accumulators packed along m (pairs), B values dup'd into both lanes.

#define SMP 132   // smem row pitch (floats); 132*4B % 16B == 0 for LDS.128

// MODE 0: outC = tot + biasA[n]
// MODE 1: mem = 0.5*mem + cur + tot + biasA - reset; spike; [DOSUM] ssum += s
template <int MODE, int DOSUM>
__global__ void __launch_bounds__(512, 1)
f32gemm_kernel(const float* __restrict__ Ag, const float* __restrict__ Bg,
               const float* __restrict__ biasA,
               float* __restrict__ memBuf, const float* __restrict__ curBuf,
               float* __restrict__ spkOut,
               float* __restrict__ ssum, float* __restrict__ outC) {
    __shared__ __align__(16) float sA[2][16][SMP];   // [k][m]
    __shared__ __align__(16) float sB[2][16][SMP];   // [k][n]

    const int tid  = threadIdx.x;
    const int warp = tid >> 5;       // 0..15
    const int lane = tid & 31;
    const int nw0  = warp * 8;       // col block for this warp
    const int lm   = lane * 4;       // row block for this lane
    const int m0   = blockIdx.y * 128;
    const int n0   = blockIdx.x * 128;

    // acc2[i2][j]: rows (lm+2*i2, lm+2*i2+1), col nw0+j
    uint64_t tot2[2][8];
    uint64_t acc2[2][8];
#pragma unroll
    for (int i = 0; i < 2; i++)
#pragma unroll
        for (int j = 0; j < 8; j++) { tot2[i][j] = 0ull; acc2[i][j] = 0ull; }

    const int nk = 64;   // 1024 / 16

    // staging: each thread 1 float4 of A and 1 of B per k-tile
    const int srow = tid >> 2;        // 0..127
    const int sk4  = (tid & 3) * 4;   // 0,4,8,12
    float4 ra, rb;

    auto gload = [&](int kt) {
        const int k0 = kt * 16 + sk4;
        ra = *(const float4*)(Ag + (size_t)(m0 + srow) * NH + k0);
        rb = *(const float4*)(Bg + (size_t)(n0 + srow) * NH + k0);
    };
    auto sts = [&](int b) {
        sA[b][sk4 + 0][srow] = ra.x;
        sA[b][sk4 + 1][srow] = ra.y;
        sA[b][sk4 + 2][srow] = ra.z;
        sA[b][sk4 + 3][srow] = ra.w;
        sB[b][sk4 + 0][srow] = rb.x;
        sB[b][sk4 + 1][srow] = rb.y;
        sB[b][sk4 + 2][srow] = rb.z;
        sB[b][sk4 + 3][srow] = rb.w;
    };

    gload(0);
    sts(0);
    __syncthreads();

    for (int kt = 0; kt < nk; kt++) {
        const int b = kt & 1;
        if (kt + 1 < nk) gload(kt + 1);

#pragma unroll
        for (int kk = 0; kk < 16; kk++) {
            // A: 4 m-values for this lane, as 2 packed pairs
            ulonglong2 aq = *(const ulonglong2*)&sA[b][kk][lm];
            // B: 8 col-values for this warp (broadcast within warp)
            float4 bv0 = *(const float4*)&sB[b][kk][nw0];
            float4 bv1 = *(const float4*)&sB[b][kk][nw0 + 4];
            uint64_t bd[8];
            bd[0] = dup2(bv0.x); bd[1] = dup2(bv0.y);
            bd[2] = dup2(bv0.z); bd[3] = dup2(bv0.w);
            bd[4] = dup2(bv1.x); bd[5] = dup2(bv1.y);
            bd[6] = dup2(bv1.z); bd[7] = dup2(bv1.w);
#pragma unroll
            for (int j = 0; j < 8; j++) {
                acc2[0][j] = fma2(aq.x, bd[j], acc2[0][j]);
                acc2[1][j] = fma2(aq.y, bd[j], acc2[1][j]);
            }
        }

        // panel boundaries: k=512 (kt 31) and k=1024 (kt 63)
        if (kt == 31 || kt == 63) {
#pragma unroll
            for (int i = 0; i < 2; i++)
#pragma unroll
                for (int j = 0; j < 8; j++) {
                    tot2[i][j] = add2(tot2[i][j], acc2[i][j]);
                    acc2[i][j] = 0ull;
                }
        }

        if (kt + 1 < nk) sts(b ^ 1);
        __syncthreads();
    }

    // ------------------------------ epilogue -------------------------------
#pragma unroll
    for (int i2 = 0; i2 < 2; i2++) {
#pragma unroll
        for (int h = 0; h < 2; h++) {
            const int row = m0 + lm + 2 * i2 + h;
            const size_t roff = (size_t)row * NH + n0 + nw0;
#pragma unroll
            for (int j = 0; j < 8; j++) {
                float2 dv = unpk2(tot2[i2][j]);
                float d = (h == 0) ? dv.x : dv.y;
                const int c = n0 + nw0 + j;
                if (MODE == 0) {
                    outC[roff + j] = __fadd_rn(d, biasA[c]);
                } else {
                    // reference order:
                    //   mem = ((((0.5*mem) + cur) + d) + bias) - reset(prev)
                    float mo = memBuf[roff + j];
                    float reset = (mo > 1.0f) ? 1.0f : 0.0f;
                    float v = __fadd_rn(__fmul_rn(0.5f, mo), curBuf[roff + j]);
                    v = __fadd_rn(v, d);
                    v = __fadd_rn(v, biasA[c]);
                    v = __fsub_rn(v, reset);
                    memBuf[roff + j] = v;
                    float s = (v > 1.0f) ? 1.0f : 0.0f;
                    spkOut[roff + j] = s;
                    if (DOSUM) ssum[roff + j] = __fadd_rn(ssum[roff + j], s);
                }
            }
        }
    }
}

// ------------------------------ output kernel ------------------------------
// out[r][o] = serial-k fma over t[r][k]*W3[o][k], then + b3[o].
__global__ void out_kernel(const float* __restrict__ t,
                           const float* __restrict__ W3,
                           const float* __restrict__ b3,
                           float* __restrict__ out) {
    int idx = blockIdx.x * blockDim.x + threadIdx.x;   // 0 .. NB*NO-1
    if (idx >= NB * NO) return;
    int row = idx / NO;
    int o   = idx - row * NO;
    const float* tr = t  + (size_t)row * NH;
    const float* wr = W3 + (size_t)o * NH;
    float acc = 0.f;
#pragma unroll 8
    for (int k = 0; k < NH; k++)
        acc = fmaf(__ldg(&tr[k]), __ldg(&wr[k]), acc);
    out[idx] = __fadd_rn(acc, b3[o]);
}

// ------------------------------- host launch -------------------------------
extern "C" void kernel_launch(void* const* d_in, const int* in_sizes, int n_in,
                              void* d_out, int out_size) {
    const float* x   = (const float*)d_in[0];
    const float* W1  = (const float*)d_in[1];
    const float* b1  = (const float*)d_in[2];
    const float* V1w = (const float*)d_in[3];
    const float* V1b = (const float*)d_in[4];
    const float* W2  = (const float*)d_in[5];
    const float* b2  = (const float*)d_in[6];
    const float* V2w = (const float*)d_in[7];
    const float* V2b = (const float*)d_in[8];
    const float* W3  = (const float*)d_in[9];
    const float* b3  = (const float*)d_in[10];
    float* out = (float*)d_out;

    void* p;
    float *spk1a, *spk1b, *spk2a, *spk2b, *mem1, *mem2, *cur1, *cur2, *ssum;
    cudaGetSymbolAddress(&p, g_spk1a); spk1a = (float*)p;
    cudaGetSymbolAddress(&p, g_spk1b); spk1b = (float*)p;
    cudaGetSymbolAddress(&p, g_spk2a); spk2a = (float*)p;
    cudaGetSymbolAddress(&p, g_spk2b); spk2b = (float*)p;
    cudaGetSymbolAddress(&p, g_mem1);  mem1  = (float*)p;
    cudaGetSymbolAddress(&p, g_mem2);  mem2  = (float*)p;
    cudaGetSymbolAddress(&p, g_cur1);  cur1  = (float*)p;
    cudaGetSymbolAddress(&p, g_cur2);  cur2  = (float*)p;
    cudaGetSymbolAddress(&p, g_ssum);  ssum  = (float*)p;

    const int nElem = NB * NH;
    init_state_kernel<<<nElem / 256, 256>>>();

    dim3 grid(NH / 128, NB / 128);   // (8, 128)
    dim3 block(512);

    // cur1 = x @ W1^T + b1
    f32gemm_kernel<0, 0><<<grid, block>>>(x, W1, b1,
                                          nullptr, nullptr, nullptr,
                                          nullptr, cur1);

    for (int st = 0; st < NSTEPS; st++) {
        const float* s1in = (st & 1) ? spk1b : spk1a;
        float*      s1out = (st & 1) ? spk1a : spk1b;
        const float* s2in = (st & 1) ? spk2b : spk2a;
        float*      s2out = (st & 1) ? spk2a : spk2b;

        // layer 1: mem1 = 0.5*mem1 + cur1 + s1in@V1w^T + V1b - reset; spike
        f32gemm_kernel<1, 0><<<grid, block>>>(s1in, V1w, V1b,
                                              mem1, cur1, s1out,
                                              nullptr, nullptr);

        // cur2 = s1out @ W2^T + b2  (separately rounded)
        f32gemm_kernel<0, 0><<<grid, block>>>(s1out, W2, b2,
                                              nullptr, nullptr, nullptr,
                                              nullptr, cur2);

        // layer 2: mem2 = 0.5*mem2 + cur2 + s2in@V2w^T + V2b - reset;
        //          spike; ssum += spike
        f32gemm_kernel<1, 1><<<grid, block>>>(s2in, V2w, V2b,
                                              mem2, cur2, s2out,
                                              ssum, nullptr);
    }

    // t = ssum/25 (rounded first), then out = t@W3^T + b3
    div25_kernel<<<nElem / 256, 256>>>(ssum);
    out_kernel<<<(NB * NO + 255) / 256, 256>>>(ssum, W3, b3, out);
}

// round 11
// speedup vs baseline: 1.2064x; 1.2064x over previous
#include <cuda_runtime.h>
#include <cstdint>
#include <cstddef>

// ---------------------------------------------------------------------------
// SNN, fp32-faithful, PASSING association (round 9): per output, fp32 FMA
// chain ascending k; K panels [0,512),[512,1024); panel sums combined with
// one rounded add. Schedule-only changes this round (arithmetic identical):
//  * panel-1 partials stashed to smem at kt=31 (frees 32 regs -> no spills
//    in MODE1/2, which regressed in round 10)
//  * B staged PRE-DUPLICATED in smem -> packed (b,b) operands load directly,
//    no dup MOVs in the inner loop
//  * dynamic smem 113.5KB, 512 threads, tile 128x128, KTILE=16, 1 sync/ktile
// ---------------------------------------------------------------------------

#define NB 16384
#define NH 1024
#define NSTEPS 25
#define NO 10

#define SMP 132        // sA row pitch (floats)
#define SBP 264        // sBd row pitch (floats, duplicated cols)
#define SA_BYTES  (2 * 16 * SMP * 4)
#define SBD_BYTES (2 * 16 * SBP * 4)
#define STASH_BYTES (16 * 512 * 8)
#define SMEM_TOTAL (SA_BYTES + SBD_BYTES + STASH_BYTES)

// ----------------------------- device scratch ------------------------------
__device__ __align__(16) float g_spk1a[NB * NH];
__device__ __align__(16) float g_spk1b[NB * NH];
__device__ __align__(16) float g_spk2a[NB * NH];
__device__ __align__(16) float g_spk2b[NB * NH];
__device__ __align__(16) float g_mem1[NB * NH];
__device__ __align__(16) float g_mem2[NB * NH];
__device__ __align__(16) float g_cur1[NB * NH];
__device__ __align__(16) float g_cur2[NB * NH];
__device__ __align__(16) float g_ssum[NB * NH];

// --------------------------- f32x2 packed helpers ---------------------------
__device__ __forceinline__ uint64_t dup2(float x) {
    uint64_t d;
    asm("mov.b64 %0, {%1, %2};" : "=l"(d) : "f"(x), "f"(x));
    return d;
}
__device__ __forceinline__ uint64_t fma2(uint64_t a, uint64_t b, uint64_t c) {
    uint64_t d;
    asm("fma.rn.f32x2 %0, %1, %2, %3;" : "=l"(d) : "l"(a), "l"(b), "l"(c));
    return d;
}
__device__ __forceinline__ uint64_t add2(uint64_t a, uint64_t b) {
    uint64_t d;
    asm("add.rn.f32x2 %0, %1, %2;" : "=l"(d) : "l"(a), "l"(b));
    return d;
}
__device__ __forceinline__ float2 unpk2(uint64_t v) {
    float lo, hi;
    asm("mov.b64 {%0, %1}, %2;" : "=f"(lo), "=f"(hi) : "l"(v));
    return make_float2(lo, hi);
}

// ------------------------------- prep kernels ------------------------------
__global__ void init_state_kernel() {
    size_t i = (size_t)blockIdx.x * blockDim.x + threadIdx.x;
    g_mem1[i] = 0.f;
    g_mem2[i] = 0.f;
    g_ssum[i] = 0.f;
    g_spk1a[i] = 0.f;
    g_spk2a[i] = 0.f;
}

__global__ void div25_kernel(float* __restrict__ s) {
    size_t i = (size_t)blockIdx.x * blockDim.x + threadIdx.x;
    s[i] = __fdiv_rn(s[i], 25.0f);
}

// ------------------------------- GEMM kernel -------------------------------
// C[m,n] = sum_k A[m,k]*B[n,k]: panels [0,512),[512,1024), serial ascending
// k within panel, one rounded add to combine (EXACTLY as passing R9/R10).
// 512 threads: warp w -> cols [w*8, w*8+8); lane -> rows [lane*4, lane*4+4).
// Accumulators m-packed (pairs); B staged duplicated so packed operands load
// directly. Panel-1 partials stashed to smem at kt=31.

// MODE 0: outC = tot + biasA[n]
// MODE 1: mem = 0.5*mem + cur + tot + biasA - reset; spike; [DOSUM] ssum += s
template <int MODE, int DOSUM>
__global__ void __launch_bounds__(512, 1)
f32gemm_kernel(const float* __restrict__ Ag, const float* __restrict__ Bg,
               const float* __restrict__ biasA,
               float* __restrict__ memBuf, const float* __restrict__ curBuf,
               float* __restrict__ spkOut,
               float* __restrict__ ssum, float* __restrict__ outC) {
    extern __shared__ __align__(16) char dsmem[];
    float* sA   = (float*)dsmem;                       // [2][16][SMP]
    float* sBd  = (float*)(dsmem + SA_BYTES);          // [2][16][SBP]
    uint64_t* stash = (uint64_t*)(dsmem + SA_BYTES + SBD_BYTES); // [16][512]

    const int tid  = threadIdx.x;
    const int warp = tid >> 5;       // 0..15
    const int lane = tid & 31;
    const int nw0  = warp * 8;       // col block for this warp
    const int lm   = lane * 4;       // row block for this lane
    const int m0   = blockIdx.y * 128;
    const int n0   = blockIdx.x * 128;

    // acc2[i2][j]: rows (lm+2*i2, lm+2*i2+1), col nw0+j
    uint64_t acc2[2][8];
#pragma unroll
    for (int i = 0; i < 2; i++)
#pragma unroll
        for (int j = 0; j < 8; j++) acc2[i][j] = 0ull;

    const int nk = 64;   // 1024 / 16

    // staging: each thread 1 float4 of A and 1 of B per k-tile
    const int srow = tid >> 2;        // 0..127
    const int sk4  = (tid & 3) * 4;   // 0,4,8,12
    float4 ra, rb;

    auto gload = [&](int kt) {
        const int k0 = kt * 16 + sk4;
        ra = *(const float4*)(Ag + (size_t)(m0 + srow) * NH + k0);
        rb = *(const float4*)(Bg + (size_t)(n0 + srow) * NH + k0);
    };
    auto sts = [&](int b) {
        float* a0 = sA + (b * 16 + sk4) * SMP + srow;
        a0[0 * SMP] = ra.x;
        a0[1 * SMP] = ra.y;
        a0[2 * SMP] = ra.z;
        a0[3 * SMP] = ra.w;
        // B duplicated: value at cols 2n and 2n+1
        uint64_t* b0 = (uint64_t*)(sBd + (b * 16 + sk4) * SBP) + srow;
        b0[0 * (SBP / 2)] = dup2(rb.x);
        b0[1 * (SBP / 2)] = dup2(rb.y);
        b0[2 * (SBP / 2)] = dup2(rb.z);
        b0[3 * (SBP / 2)] = dup2(rb.w);
    };

    gload(0);
    sts(0);
    __syncthreads();

    for (int kt = 0; kt < nk; kt++) {
        const int b = kt & 1;
        if (kt + 1 < nk) gload(kt + 1);

        const float* sAb  = sA  + b * 16 * SMP;
        const float* sBdb = sBd + b * 16 * SBP;
#pragma unroll
        for (int kk = 0; kk < 16; kk++) {
            // A: 4 m-values as 2 packed pairs (one LDS.128)
            ulonglong2 aq = *(const ulonglong2*)(sAb + kk * SMP + lm);
            // B: 8 duplicated col-values = 8 u64, broadcast LDS.128 x4
            const uint64_t* brow =
                (const uint64_t*)(sBdb + kk * SBP + 2 * nw0);
#pragma unroll
            for (int half = 0; half < 2; half++) {
                ulonglong2 b01 = *(const ulonglong2*)(brow + half * 4);
                ulonglong2 b23 = *(const ulonglong2*)(brow + half * 4 + 2);
                const int j0 = half * 4;
                acc2[0][j0 + 0] = fma2(aq.x, b01.x, acc2[0][j0 + 0]);
                acc2[1][j0 + 0] = fma2(aq.y, b01.x, acc2[1][j0 + 0]);
                acc2[0][j0 + 1] = fma2(aq.x, b01.y, acc2[0][j0 + 1]);
                acc2[1][j0 + 1] = fma2(aq.y, b01.y, acc2[1][j0 + 1]);
                acc2[0][j0 + 2] = fma2(aq.x, b23.x, acc2[0][j0 + 2]);
                acc2[1][j0 + 2] = fma2(aq.y, b23.x, acc2[1][j0 + 2]);
                acc2[0][j0 + 3] = fma2(aq.x, b23.y, acc2[0][j0 + 3]);
                acc2[1][j0 + 3] = fma2(aq.y, b23.y, acc2[1][j0 + 3]);
            }
        }

        // panel boundary k=512: stash panel-1 sums, restart accumulator
        if (kt == 31) {
#pragma unroll
            for (int i2 = 0; i2 < 2; i2++)
#pragma unroll
                for (int j = 0; j < 8; j++) {
                    stash[(i2 * 8 + j) * 512 + tid] = acc2[i2][j];
                    acc2[i2][j] = 0ull;
                }
        }

        if (kt + 1 < nk) sts(b ^ 1);
        __syncthreads();
    }

    // ------------------------------ epilogue -------------------------------
    // tot = panel1 + panel2 (one rounded add per lane, as in R9/R10)
#pragma unroll
    for (int i2 = 0; i2 < 2; i2++) {
#pragma unroll
        for (int j = 0; j < 8; j++) {
            uint64_t tot = add2(stash[(i2 * 8 + j) * 512 + tid], acc2[i2][j]);
            float2 dv = unpk2(tot);
#pragma unroll
            for (int h = 0; h < 2; h++) {
                const int row = m0 + lm + 2 * i2 + h;
                const int c   = n0 + nw0 + j;
                const size_t off = (size_t)row * NH + c;
                float d = (h == 0) ? dv.x : dv.y;
                if (MODE == 0) {
                    outC[off] = __fadd_rn(d, biasA[c]);
                } else {
                    // reference order:
                    //   mem = ((((0.5*mem) + cur) + d) + bias) - reset(prev)
                    float mo = memBuf[off];
                    float reset = (mo > 1.0f) ? 1.0f : 0.0f;
                    float v = __fadd_rn(__fmul_rn(0.5f, mo), curBuf[off]);
                    v = __fadd_rn(v, d);
                    v = __fadd_rn(v, biasA[c]);
                    v = __fsub_rn(v, reset);
                    memBuf[off] = v;
                    float s = (v > 1.0f) ? 1.0f : 0.0f;
                    spkOut[off] = s;
                    if (DOSUM) ssum[off] = __fadd_rn(ssum[off], s);
                }
            }
        }
    }
}

// ------------------------------ output kernel ------------------------------
__global__ void out_kernel(const float* __restrict__ t,
                           const float* __restrict__ W3,
                           const float* __restrict__ b3,
                           float* __restrict__ out) {
    int idx = blockIdx.x * blockDim.x + threadIdx.x;   // 0 .. NB*NO-1
    if (idx >= NB * NO) return;
    int row = idx / NO;
    int o   = idx - row * NO;
    const float* tr = t  + (size_t)row * NH;
    const float* wr = W3 + (size_t)o * NH;
    float acc = 0.f;
#pragma unroll 8
    for (int k = 0; k < NH; k++)
        acc = fmaf(__ldg(&tr[k]), __ldg(&wr[k]), acc);
    out[idx] = __fadd_rn(acc, b3[o]);
}

// ------------------------------- host launch -------------------------------
extern "C" void kernel_launch(void* const* d_in, const int* in_sizes, int n_in,
                              void* d_out, int out_size) {
    const float* x   = (const float*)d_in[0];
    const float* W1  = (const float*)d_in[1];
    const float* b1  = (const float*)d_in[2];
    const float* V1w = (const float*)d_in[3];
    const float* V1b = (const float*)d_in[4];
    const float* W2  = (const float*)d_in[5];
    const float* b2  = (const float*)d_in[6];
    const float* V2w = (const float*)d_in[7];
    const float* V2b = (const float*)d_in[8];
    const float* W3  = (const float*)d_in[9];
    const float* b3  = (const float*)d_in[10];
    float* out = (float*)d_out;

    void* p;
    float *spk1a, *spk1b, *spk2a, *spk2b, *mem1, *mem2, *cur1, *cur2, *ssum;
    cudaGetSymbolAddress(&p, g_spk1a); spk1a = (float*)p;
    cudaGetSymbolAddress(&p, g_spk1b); spk1b = (float*)p;
    cudaGetSymbolAddress(&p, g_spk2a); spk2a = (float*)p;
    cudaGetSymbolAddress(&p, g_spk2b); spk2b = (float*)p;
    cudaGetSymbolAddress(&p, g_mem1);  mem1  = (float*)p;
    cudaGetSymbolAddress(&p, g_mem2);  mem2  = (float*)p;
    cudaGetSymbolAddress(&p, g_cur1);  cur1  = (float*)p;
    cudaGetSymbolAddress(&p, g_cur2);  cur2  = (float*)p;
    cudaGetSymbolAddress(&p, g_ssum);  ssum  = (float*)p;

    // dynamic smem > 48KB needs an explicit opt-in (idempotent host calls)
    cudaFuncSetAttribute(f32gemm_kernel<0, 0>,
                         cudaFuncAttributeMaxDynamicSharedMemorySize, SMEM_TOTAL);
    cudaFuncSetAttribute(f32gemm_kernel<1, 0>,
                         cudaFuncAttributeMaxDynamicSharedMemorySize, SMEM_TOTAL);
    cudaFuncSetAttribute(f32gemm_kernel<1, 1>,
                         cudaFuncAttributeMaxDynamicSharedMemorySize, SMEM_TOTAL);

    const int nElem = NB * NH;
    init_state_kernel<<<nElem / 256, 256>>>();

    dim3 grid(NH / 128, NB / 128);   // (8, 128)
    dim3 block(512);

    // cur1 = x @ W1^T + b1
    f32gemm_kernel<0, 0><<<grid, block, SMEM_TOTAL>>>(
        x, W1, b1, nullptr, nullptr, nullptr, nullptr, cur1);

    for (int st = 0; st < NSTEPS; st++) {
        const float* s1in = (st & 1) ? spk1b : spk1a;
        float*      s1out = (st & 1) ? spk1a : spk1b;
        const float* s2in = (st & 1) ? spk2b : spk2a;
        float*      s2out = (st & 1) ? spk2a : spk2b;

        // layer 1: mem1 = 0.5*mem1 + cur1 + s1in@V1w^T + V1b - reset; spike
        f32gemm_kernel<1, 0><<<grid, block, SMEM_TOTAL>>>(
            s1in, V1w, V1b, mem1, cur1, s1out, nullptr, nullptr);

        // cur2 = s1out @ W2^T + b2  (separately rounded)
        f32gemm_kernel<0, 0><<<grid, block, SMEM_TOTAL>>>(
            s1out, W2, b2, nullptr, nullptr, nullptr, nullptr, cur2);

        // layer 2: mem2 = 0.5*mem2 + cur2 + s2in@V2w^T + V2b - reset;
        //          spike; ssum += spike
        f32gemm_kernel<1, 1><<<grid, block, SMEM_TOTAL>>>(
            s2in, V2w, V2b, mem2, cur2, s2out, ssum, nullptr);
    }

    // t = ssum/25 (rounded first), then out = t@W3^T + b3
    div25_kernel<<<nElem / 256, 256>>>(ssum);
    out_kernel<<<(NB * NO + 255) / 256, 256>>>(ssum, W3, b3, out);
}